// round 12
// baseline (speedup 1.0000x reference)
#include <cuda_runtime.h>
#include <cstdint>
typedef unsigned long long u64;

#define NBINS   2048
#define HALF    (NBINS / 2)
#define BDIM    4          // batch (fixed for this problem)
#define RMAX    7
#define NC      72         // chunks per batch image -> grid = 4*72 = 288 CTAs
#define THREADS 512        // 2 CTAs/SM -> 32 warps/SM, reg budget 64

// Scratch (static device globals: allocation-free rule)
__device__ int    g_part16[BDIM * NC * RMAX * HALF];  // packed int16 pairs
__device__ int    g_merged[RMAX * BDIM * NBINS];
__device__ int    g_cnt[BDIM * NC * RMAX];
__device__ double g_pnum[RMAX * BDIM];
__device__ int    g_pden[RMAX * BDIM];
__device__ int    g_bar1 = 0;                         // grid barrier (self-reset)
__device__ int    g_bar2 = 0;                         // grid barrier (self-reset)
__device__ int    g_ticket = 0;                       // finalize ticket (self-reset)

__device__ __forceinline__ int binf(float x) {
    int k = __float2int_rz(x * (float)NBINS);
    return min(max(k, 0), NBINS - 1);
}

// Persistent fused kernel: hist -> barrier -> merge -> barrier -> scan+finalize.
// 288 CTAs at 2/SM: all co-resident (288 <= 2*148) => spin barriers safe.
// Phase A processes 8 voxels/thread/iter: 16 independent LDG.128 in flight.
template <int RR>
__global__ void __launch_bounds__(THREADS, 2)
fused_kernel(const float* __restrict__ pred,
             const float* __restrict__ tgt,
             const int*   __restrict__ mask,  // bool serialized as int32, [R,B,V]
             float* __restrict__ outp,
             int V, int CH, int RB, int NB)
{
    extern __shared__ int sh[];               // RR * NBINS signed counters
    __shared__ int scnt[RR];
    __shared__ int wsum[17];
    __shared__ long long wacc[16];
    __shared__ int sden;

    const int t   = threadIdx.x;
    const int cid = blockIdx.x;
    const int PACKR = RR * HALF;

    // ================= Phase A: histogram =================
    #pragma unroll
    for (int j = t; j < RR * NBINS; j += THREADS) sh[j] = 0;
    if (t < RR) scnt[t] = 0;

    {
        const int b = cid & (BDIM - 1);
        const int c = cid >> 2;
        const size_t rstride = (size_t)BDIM * (size_t)V;

        const float* pp = pred + (size_t)b * V;
        const float* gp = tgt  + (size_t)b * V;
        const int*   mp = mask + (size_t)b * V;

        const int start = c * CH;
        const int end   = min(V, start + CH);

        u64 cntAcc = 0ull;                    // six 10-bit per-ROI counters
        __syncthreads();

        for (int off = start + t * 8; off < end; off += THREADS * 8) {
            // 4 independent float4 loads
            float4 pv0 = __ldcs(reinterpret_cast<const float4*>(pp + off));
            float4 pv1 = __ldcs(reinterpret_cast<const float4*>(pp + off + 4));
            float4 gv0 = __ldcs(reinterpret_cast<const float4*>(gp + off));
            float4 gv1 = __ldcs(reinterpret_cast<const float4*>(gp + off + 4));

            int pb0 = binf(pv0.x), pb1 = binf(pv0.y), pb2 = binf(pv0.z), pb3 = binf(pv0.w);
            int pb4 = binf(pv1.x), pb5 = binf(pv1.y), pb6 = binf(pv1.z), pb7 = binf(pv1.w);
            int qb0 = binf(gv0.x), qb1 = binf(gv0.y), qb2 = binf(gv0.z), qb3 = binf(gv0.w);
            int qb4 = binf(gv1.x), qb5 = binf(gv1.y), qb6 = binf(gv1.z), qb7 = binf(gv1.w);

            const int* m = mp + off;
            #pragma unroll
            for (int r = 0; r < RR; r++) {
                int4 mv0 = __ldcs(reinterpret_cast<const int4*>(m));
                int4 mv1 = __ldcs(reinterpret_cast<const int4*>(m + 4));
                m += rstride;
                int* h = sh + r * NBINS;
                if (mv0.x) { atomicAdd(h + pb0, 1); atomicAdd(h + qb0, -1); }
                if (mv0.y) { atomicAdd(h + pb1, 1); atomicAdd(h + qb1, -1); }
                if (mv0.z) { atomicAdd(h + pb2, 1); atomicAdd(h + qb2, -1); }
                if (mv0.w) { atomicAdd(h + pb3, 1); atomicAdd(h + qb3, -1); }
                if (mv1.x) { atomicAdd(h + pb4, 1); atomicAdd(h + qb4, -1); }
                if (mv1.y) { atomicAdd(h + pb5, 1); atomicAdd(h + qb5, -1); }
                if (mv1.z) { atomicAdd(h + pb6, 1); atomicAdd(h + qb6, -1); }
                if (mv1.w) { atomicAdd(h + pb7, 1); atomicAdd(h + qb7, -1); }
                cntAcc += (u64)(unsigned)(mv0.x + mv0.y + mv0.z + mv0.w +
                                          mv1.x + mv1.y + mv1.z + mv1.w) << (10 * r);
            }
        }
        __syncthreads();

        // flush: pack bin pairs (per-chunk counts provably fit int16)
        int* out = g_part16 + (size_t)cid * PACKR;
        #pragma unroll
        for (int j = t; j < PACKR; j += THREADS)
            out[j] = (sh[2 * j] & 0xFFFF) | (sh[2 * j + 1] << 16);

        // per-ROI masked counts
        #pragma unroll
        for (int r = 0; r < RR; r++) {
            int v = (int)((cntAcc >> (10 * r)) & 1023u);
            #pragma unroll
            for (int d = 16; d; d >>= 1) v += __shfl_down_sync(0xffffffffu, v, d);
            if ((t & 31) == 0 && v) atomicAdd(&scnt[r], v);
        }
        __syncthreads();
        if (t < RR) g_cnt[cid * RR + t] = scnt[t];
    }

    // ---- grid barrier 1 ----
    __threadfence();
    __syncthreads();
    if (t == 0) {
        atomicAdd(&g_bar1, 1);
        while (*(volatile int*)&g_bar1 < NB) { }
    }
    __syncthreads();
    __threadfence();

    // ================= Phase B: merge =================
    // column idx = rb*HALF + pi; each active thread sums NC chunk partials.
    {
        const int total = RB * HALF;          // 24576 columns
        for (int idx = cid * THREADS + t; idx < total; idx += NB * THREADS) {
            int rb = idx >> 10;               // HALF == 1024
            int pi = idx & (HALF - 1);
            int r  = rb >> 2;
            int b  = rb & 3;
            const int* base = g_part16 + (size_t)b * PACKR + r * HALF + pi;
            int s0 = 0, s1 = 0;
            #pragma unroll 8
            for (int c = 0; c < NC; c++) {
                int v = base[(size_t)c * (BDIM * PACKR)];
                s0 += (int)(short)v;
                s1 += v >> 16;
            }
            *reinterpret_cast<int2*>(g_merged + (size_t)rb * NBINS + 2 * pi)
                = make_int2(s0, s1);
        }
    }

    // ---- grid barrier 2 ----
    __threadfence();
    __syncthreads();
    if (t == 0) atomicAdd(&g_bar2, 1);
    if (cid >= RB) return;                    // merge-only CTAs done
    if (t == 0) {
        while (*(volatile int*)&g_bar2 < NB) { }
    }
    __syncthreads();
    __threadfence();

    // ================= Phase C: scan (RB CTAs) + finalize =================
    {
        const int rb = cid;
        const int b  = rb & 3;
        const int r  = rb >> 2;
        const int lane = t & 31, w = t >> 5;  // 16 warps

        // thread t owns bins [4t, 4t+4)
        int4 v = *reinterpret_cast<const int4*>(g_merged + (size_t)rb * NBINS + t * 4);
        int local = v.x + v.y + v.z + v.w;

        int x = local;                        // warp inclusive scan
        #pragma unroll
        for (int d = 1; d < 32; d <<= 1) {
            int y = __shfl_up_sync(0xffffffffu, x, d);
            if (lane >= d) x += y;
        }
        if (lane == 31) wsum[w + 1] = x;
        if (t == 0) { sden = 0; wsum[0] = 0; }
        __syncthreads();
        if (t == 0)
            for (int i = 1; i < 16; i++) wsum[i + 1] += wsum[i];
        __syncthreads();

        int cum = wsum[w] + x - local;        // exclusive prefix for this thread
        int acc = 0;
        cum += v.x; acc += cum < 0 ? -cum : cum;
        cum += v.y; acc += cum < 0 ? -cum : cum;
        cum += v.z; acc += cum < 0 ? -cum : cum;
        cum += v.w; acc += cum < 0 ? -cum : cum;

        long long a = acc;
        #pragma unroll
        for (int d = 16; d; d >>= 1) a += __shfl_down_sync(0xffffffffu, a, d);
        if (lane == 0) wacc[w] = a;

        if (t < NC) atomicAdd(&sden, g_cnt[(t * BDIM + b) * RR + r]);
        __syncthreads();

        if (t == 0) {
            long long s = 0;
            #pragma unroll
            for (int i = 0; i < 16; i++) s += wacc[i];
            g_pnum[rb] = (double)s * (52.0 / (double)NBINS);
            g_pden[rb] = sden;
            __threadfence();

            int old = atomicAdd(&g_ticket, 1);
            if (old == RB - 1) {              // last scanner: finalize
                g_ticket = 0;                 // self-reset for graph replays
                g_bar1   = 0;
                g_bar2   = 0;
                __threadfence();
                volatile double* vn = g_pnum;
                volatile int*    vd = g_pden;
                double ls = 0.0;
                int cv = 0;
                for (int bb = 0; bb < BDIM; bb++) {
                    double num = 0.0; long long dn = 0;
                    for (int rr = 0; rr < RB / BDIM; rr++) {
                        num += vn[rr * BDIM + bb];
                        dn  += vd[rr * BDIM + bb];
                    }
                    if (dn > 0) {
                        ls += num / (double)(dn < 1 ? 1 : dn);
                        cv++;
                    }
                }
                outp[0] = (float)(ls / (double)(cv > 0 ? cv : 1));
            }
        }
    }
}

template <int RR>
static void launch_fused(const float* p, const float* g, const int* m,
                         float* o, int V, int CH, int RB)
{
    int smem = RR * NBINS * 4;                // 48 KB for RR=6 -> 2 CTAs/SM
    cudaFuncSetAttribute(fused_kernel<RR>, cudaFuncAttributeMaxDynamicSharedMemorySize, smem);
    int NB = BDIM * NC;                       // 288 <= 2*148: all co-resident
    fused_kernel<RR><<<NB, THREADS, smem>>>(p, g, m, o, V, CH, RB, NB);
}

extern "C" void kernel_launch(void* const* d_in, const int* in_sizes, int n_in,
                              void* d_out, int out_size)
{
    const float* pred = (const float*)d_in[0];
    const float* tgt  = (const float*)d_in[1];
    const int*   mask = (const int*)d_in[2];

    int BV = in_sizes[0];                     // B*V = 4194304
    int V  = BV / BDIM;                       // 1048576
    int R  = in_sizes[2] / BV;                // 6
    int RB = R * BDIM;                        // 24
    int CH = ((V + NC - 1) / NC + 7) & ~7;    // chunk, multiple of 8

    float* o = (float*)d_out;
    switch (R) {
        case 1: launch_fused<1>(pred, tgt, mask, o, V, CH, RB); break;
        case 2: launch_fused<2>(pred, tgt, mask, o, V, CH, RB); break;
        case 3: launch_fused<3>(pred, tgt, mask, o, V, CH, RB); break;
        case 4: launch_fused<4>(pred, tgt, mask, o, V, CH, RB); break;
        case 5: launch_fused<5>(pred, tgt, mask, o, V, CH, RB); break;
        case 7: launch_fused<7>(pred, tgt, mask, o, V, CH, RB); break;
        default:
        case 6: launch_fused<6>(pred, tgt, mask, o, V, CH, RB); break;
    }
}